// round 11
// baseline (speedup 1.0000x reference)
#include <cuda_runtime.h>
#include <cuda_bf16.h>
#include <math.h>
#include <stdint.h>

// Problem constants
#define BB   8
#define NN   4096
#define CC   768
#define HH   8
#define HD   96
#define BN   32768
#define C3   2304
#define BHCNT 64

// ---------------------------------------------------------------------------
// Scratch (device globals: allocation-free, graph-capturable)
// ---------------------------------------------------------------------------
__device__ float g_qkv[(size_t)BN * C3];               // [bn][3C] fp32 qkv
__device__ __nv_bfloat16 g_xhi[(size_t)BN * CC];       // x split
__device__ __nv_bfloat16 g_xlo[(size_t)BN * CC];
__device__ __nv_bfloat16 g_chi[(size_t)BN * CC];       // ctx split (av output)
__device__ __nv_bfloat16 g_clo[(size_t)BN * CC];
__device__ __nv_bfloat16 g_wq_hi[(size_t)C3 * CC];     // Wqkv^T [2304][768]
__device__ __nv_bfloat16 g_wq_lo[(size_t)C3 * CC];
__device__ __nv_bfloat16 g_wp_hi[(size_t)CC * CC];     // Wproj^T [768][768]
__device__ __nv_bfloat16 g_wp_lo[(size_t)CC * CC];
__device__ float g_gram[BHCNT * HD * HD];
__device__ float g_attn[BHCNT * HD * HD];
__device__ float g_qss[BHCNT * HD];
__device__ float g_kss[BHCNT * HD];

// ---------------------------------------------------------------------------
// Baseline-PTX helpers (sm_80+, no 'a'-gated features)
// ---------------------------------------------------------------------------
__device__ __forceinline__ uint32_t smem_u32(const void* p) {
    uint32_t a;
    asm("{ .reg .u64 t; cvta.to.shared.u64 t, %1; cvt.u32.u64 %0, t; }" : "=r"(a) : "l"(p));
    return a;
}
__device__ __forceinline__ void cp16(uint32_t saddr, const void* g) {
    asm volatile("cp.async.cg.shared.global [%0], [%1], 16;" :: "r"(saddr), "l"(g) : "memory");
}
__device__ __forceinline__ void cp_commit() {
    asm volatile("cp.async.commit_group;" ::: "memory");
}
__device__ __forceinline__ void cp_wait0() {
    asm volatile("cp.async.wait_group 0;" ::: "memory");
}
__device__ __forceinline__ void ldsm4(uint32_t& r0, uint32_t& r1, uint32_t& r2, uint32_t& r3,
                                      uint32_t addr) {
    asm volatile("ldmatrix.sync.aligned.m8n8.x4.shared.b16 {%0,%1,%2,%3}, [%4];"
                 : "=r"(r0), "=r"(r1), "=r"(r2), "=r"(r3) : "r"(addr));
}
__device__ __forceinline__ void mma16816(float* d, const uint32_t* a, const uint32_t* b) {
    asm volatile(
        "mma.sync.aligned.m16n8k16.row.col.f32.bf16.bf16.f32 "
        "{%0,%1,%2,%3}, {%4,%5,%6,%7}, {%8,%9}, {%0,%1,%2,%3};"
        : "+f"(d[0]), "+f"(d[1]), "+f"(d[2]), "+f"(d[3])
        : "r"(a[0]), "r"(a[1]), "r"(a[2]), "r"(a[3]), "r"(b[0]), "r"(b[1]));
}

// ---------------------------------------------------------------------------
// bf16 hi/lo split conversion for x
// ---------------------------------------------------------------------------
__global__ void conv_x_kernel(const float* __restrict__ x) {
    size_t i = (size_t)blockIdx.x * 256 + threadIdx.x;
    const size_t total = (size_t)BN * CC / 4;
    for (; i < total; i += (size_t)gridDim.x * 256) {
        float4 v = ((const float4*)x)[i];
        __nv_bfloat16 h0 = __float2bfloat16(v.x), h1 = __float2bfloat16(v.y);
        __nv_bfloat16 h2 = __float2bfloat16(v.z), h3 = __float2bfloat16(v.w);
        __nv_bfloat16 l0 = __float2bfloat16(v.x - __bfloat162float(h0));
        __nv_bfloat16 l1 = __float2bfloat16(v.y - __bfloat162float(h1));
        __nv_bfloat16 l2 = __float2bfloat16(v.z - __bfloat162float(h2));
        __nv_bfloat16 l3 = __float2bfloat16(v.w - __bfloat162float(h3));
        g_xhi[i*4+0] = h0; g_xhi[i*4+1] = h1; g_xhi[i*4+2] = h2; g_xhi[i*4+3] = h3;
        g_xlo[i*4+0] = l0; g_xlo[i*4+1] = l1; g_xlo[i*4+2] = l2; g_xlo[i*4+3] = l3;
    }
}

// ---------------------------------------------------------------------------
// Tiled transpose + hi/lo split: out[n][k] = W[k][n], W is [K][Nn].
// 32x32 tiles, coalesced on both sides. grid (Nn/32, K/32), 256 threads.
// ---------------------------------------------------------------------------
__global__ __launch_bounds__(256) void transp_kernel(
    const float* __restrict__ W,
    __nv_bfloat16* __restrict__ Thi, __nv_bfloat16* __restrict__ Tlo,
    int K, int Nn)
{
    __shared__ float sm[32][33];
    const int n0 = blockIdx.x * 32, k0 = blockIdx.y * 32;
    const int c = threadIdx.x & 31, r = threadIdx.x >> 5;   // 8 row-groups

#pragma unroll
    for (int rr = 0; rr < 4; rr++)
        sm[r + rr * 8][c] = W[(size_t)(k0 + r + rr * 8) * Nn + n0 + c];
    __syncthreads();

#pragma unroll
    for (int rr = 0; rr < 4; rr++) {
        const int n = n0 + r + rr * 8;
        const float v = sm[c][r + rr * 8];
        __nv_bfloat16 h = __float2bfloat16(v);
        Thi[(size_t)n * K + k0 + c] = h;
        Tlo[(size_t)n * K + k0 + c] = __float2bfloat16(v - __bfloat162float(h));
    }
}

// ---------------------------------------------------------------------------
// HMMA bf16-split GEMM v2: C[m][n] = sum_k A[m][k]*B[n][k]  (fp32-accurate)
// 3 split terms restructured to share SMEM tiles:
//   Loop A (12 chunks): load {Ahi, Bhi, Blo}; compute hi*hi + hi*lo (A frags reused)
//   Loop B (12 chunks): load {Alo, Bhi}; compute lo*hi
// CTA tile 128x128, 8 warps of 64x32, K-chunk 64, cp.async double buffer.
// SMEM: 2 stages x 48KB = 96KB. 2 CTAs/SM.
// ---------------------------------------------------------------------------
#define GEMM_SMEM_BYTES 98304
#define STAGE_BYTES 49152u

__global__ __launch_bounds__(256, 2) void gemm_mma(
    const __nv_bfloat16* __restrict__ Ahi, const __nv_bfloat16* __restrict__ Alo,
    const __nv_bfloat16* __restrict__ Bhi, const __nv_bfloat16* __restrict__ Blo,
    float* __restrict__ C, const float* __restrict__ bias, int ldc)
{
    extern __shared__ char smem[];
    const uint32_t sb = smem_u32(smem);
    const int t = threadIdx.x;
    const int lane = t & 31, wid = t >> 5;
    const int m0 = blockIdx.y * 128;
    const int n0 = blockIdx.x * 128;
    const int wm = (wid & 1) * 64;       // warp m-offset
    const int wn = (wid >> 1) * 32;      // warp n-offset

    // loader mapping: 4 x 16B per 16KB tile per thread (SW128 swizzle)
    int lso[4], lgo[4];
#pragma unroll
    for (int i = 0; i < 4; i++) {
        int idx = t + 256 * i, row = idx >> 3, seg = idx & 7;
        lso[i] = row * 128 + ((seg * 16) ^ ((row & 7) << 4));
        lgo[i] = row * CC + seg * 8;
    }

    // ldmatrix lane addressing
    const int q = lane >> 3, r = lane & 7;
    const uint32_t rx = (uint32_t)(r << 4);
    const int aro = r + (q & 1) * 8;
    const int akb = (q >> 1) * 16;
    const int bro = r + (q >> 1) * 8;
    const int bkb = (q & 1) * 16;
    uint32_t Ab[2][4], Bb1[2][2], Bb2[2][2];
#pragma unroll
    for (int s = 0; s < 2; s++) {
        const uint32_t base = sb + s * STAGE_BYTES;
#pragma unroll
        for (int mt = 0; mt < 4; mt++)
            Ab[s][mt] = base + (uint32_t)(wm + mt * 16 + aro) * 128u;
#pragma unroll
        for (int n2 = 0; n2 < 2; n2++) {
            Bb1[s][n2] = base + 16384u + (uint32_t)(wn + n2 * 16 + bro) * 128u;
            Bb2[s][n2] = base + 32768u + (uint32_t)(wn + n2 * 16 + bro) * 128u;
        }
    }

    float acc[4][4][4];
#pragma unroll
    for (int mt = 0; mt < 4; mt++)
#pragma unroll
        for (int nt = 0; nt < 4; nt++)
#pragma unroll
            for (int i = 0; i < 4; i++) acc[mt][nt][i] = 0.0f;

    // ================= Loop A: hi*hi + hi*lo ==================
    {
#pragma unroll
        for (int i = 0; i < 4; i++) {
            cp16(sb + lso[i],          Ahi + (size_t)m0 * CC + lgo[i]);
            cp16(sb + 16384u + lso[i], Bhi + (size_t)n0 * CC + lgo[i]);
            cp16(sb + 32768u + lso[i], Blo + (size_t)n0 * CC + lgo[i]);
        }
        cp_commit(); cp_wait0(); __syncthreads();
    }
    for (int c = 0; c < 12; c++) {
        const int s = c & 1;
        if (c < 11) {
            const int k0 = (c + 1) * 64;
            const uint32_t st = sb + (uint32_t)((c + 1) & 1) * STAGE_BYTES;
#pragma unroll
            for (int i = 0; i < 4; i++) {
                cp16(st + lso[i],          Ahi + (size_t)m0 * CC + k0 + lgo[i]);
                cp16(st + 16384u + lso[i], Bhi + (size_t)n0 * CC + k0 + lgo[i]);
                cp16(st + 32768u + lso[i], Blo + (size_t)n0 * CC + k0 + lgo[i]);
            }
            cp_commit();
        }
#pragma unroll
        for (int kk = 0; kk < 4; kk++) {
            const uint32_t ak = ((uint32_t)(kk * 32 + akb)) ^ rx;
            const uint32_t bk = ((uint32_t)(kk * 32 + bkb)) ^ rx;
            uint32_t a[4][4];
#pragma unroll
            for (int mt = 0; mt < 4; mt++)
                ldsm4(a[mt][0], a[mt][1], a[mt][2], a[mt][3], Ab[s][mt] + ak);
            uint32_t bfr[4][2];
#pragma unroll
            for (int n2 = 0; n2 < 2; n2++) {
                uint32_t r0, r1, r2, r3;
                ldsm4(r0, r1, r2, r3, Bb1[s][n2] + bk);
                bfr[n2 * 2][0] = r0;     bfr[n2 * 2][1] = r1;
                bfr[n2 * 2 + 1][0] = r2; bfr[n2 * 2 + 1][1] = r3;
            }
#pragma unroll
            for (int nt = 0; nt < 4; nt++)
#pragma unroll
                for (int mt = 0; mt < 4; mt++)
                    mma16816(acc[mt][nt], a[mt], bfr[nt]);
            // reuse A fragments with Blo
#pragma unroll
            for (int n2 = 0; n2 < 2; n2++) {
                uint32_t r0, r1, r2, r3;
                ldsm4(r0, r1, r2, r3, Bb2[s][n2] + bk);
                bfr[n2 * 2][0] = r0;     bfr[n2 * 2][1] = r1;
                bfr[n2 * 2 + 1][0] = r2; bfr[n2 * 2 + 1][1] = r3;
            }
#pragma unroll
            for (int nt = 0; nt < 4; nt++)
#pragma unroll
                for (int mt = 0; mt < 4; mt++)
                    mma16816(acc[mt][nt], a[mt], bfr[nt]);
        }
        if (c < 11) { cp_wait0(); __syncthreads(); }
    }

    // ================= Loop B: lo*hi ==================
    {
#pragma unroll
        for (int i = 0; i < 4; i++) {
            cp16(sb + lso[i],          Alo + (size_t)m0 * CC + lgo[i]);
            cp16(sb + 16384u + lso[i], Bhi + (size_t)n0 * CC + lgo[i]);
        }
        cp_commit(); cp_wait0(); __syncthreads();
    }
    for (int c = 0; c < 12; c++) {
        const int s = c & 1;
        if (c < 11) {
            const int k0 = (c + 1) * 64;
            const uint32_t st = sb + (uint32_t)((c + 1) & 1) * STAGE_BYTES;
#pragma unroll
            for (int i = 0; i < 4; i++) {
                cp16(st + lso[i],          Alo + (size_t)m0 * CC + k0 + lgo[i]);
                cp16(st + 16384u + lso[i], Bhi + (size_t)n0 * CC + k0 + lgo[i]);
            }
            cp_commit();
        }
#pragma unroll
        for (int kk = 0; kk < 4; kk++) {
            const uint32_t ak = ((uint32_t)(kk * 32 + akb)) ^ rx;
            const uint32_t bk = ((uint32_t)(kk * 32 + bkb)) ^ rx;
            uint32_t a[4][4];
#pragma unroll
            for (int mt = 0; mt < 4; mt++)
                ldsm4(a[mt][0], a[mt][1], a[mt][2], a[mt][3], Ab[s][mt] + ak);
            uint32_t bfr[4][2];
#pragma unroll
            for (int n2 = 0; n2 < 2; n2++) {
                uint32_t r0, r1, r2, r3;
                ldsm4(r0, r1, r2, r3, Bb1[s][n2] + bk);
                bfr[n2 * 2][0] = r0;     bfr[n2 * 2][1] = r1;
                bfr[n2 * 2 + 1][0] = r2; bfr[n2 * 2 + 1][1] = r3;
            }
#pragma unroll
            for (int nt = 0; nt < 4; nt++)
#pragma unroll
                for (int mt = 0; mt < 4; mt++)
                    mma16816(acc[mt][nt], a[mt], bfr[nt]);
        }
        if (c < 11) { cp_wait0(); __syncthreads(); }
    }

    // --- epilogue: direct global stores of D fragments ---
    const int mrow = lane >> 2;
    const int ncol = (lane & 3) * 2;
#pragma unroll
    for (int nt = 0; nt < 4; nt++) {
        const int col = n0 + wn + nt * 8 + ncol;
        float b0 = 0.0f, b1 = 0.0f;
        if (bias != nullptr) { b0 = bias[col]; b1 = bias[col + 1]; }
#pragma unroll
        for (int mt = 0; mt < 4; mt++) {
            const int m = m0 + wm + mt * 16 + mrow;
            float2 v0 = make_float2(acc[mt][nt][0] + b0, acc[mt][nt][1] + b1);
            float2 v1 = make_float2(acc[mt][nt][2] + b0, acc[mt][nt][3] + b1);
            *(float2*)(C + (size_t)m * ldc + col) = v0;
            *(float2*)(C + (size_t)(m + 8) * ldc + col) = v1;
        }
    }
}

// ---------------------------------------------------------------------------
// Zero reduction scratch
// ---------------------------------------------------------------------------
__global__ void zero_kernel() {
    int i = blockIdx.x * 256 + threadIdx.x;
    if (i < BHCNT * HD * HD) g_gram[i] = 0.0f;
    if (i < BHCNT * HD) { g_qss[i] = 0.0f; g_kss[i] = 0.0f; }
}

// ---------------------------------------------------------------------------
// Split-K Gram + norms (float2-vectorized smem reads)
// ---------------------------------------------------------------------------
__global__ __launch_bounds__(256) void gram_kernel() {
    const int bh = blockIdx.x;
    const int s  = blockIdx.y;
    const int b  = bh >> 3, h = bh & 7;
    const int NSPLIT = NN / 8;
    const int nbase = s * NSPLIT;

    __shared__ __align__(16) float Qs[16][96];
    __shared__ __align__(16) float Ks[16][96];

    const int t  = threadIdx.x;
    const int tx = t & 15, ty = t >> 4;

    float acc[6][6];
#pragma unroll
    for (int i = 0; i < 6; i++)
#pragma unroll
        for (int j = 0; j < 6; j++) acc[i][j] = 0.0f;
    float nss = 0.0f;

    const float* qbase = g_qkv + (size_t)b * NN * C3 + h * HD;
    const float* kbase = qbase + CC;

    for (int n0 = nbase; n0 < nbase + NSPLIT; n0 += 16) {
        for (int i = t; i < 16 * 96; i += 256) {
            int nl = i / 96, d = i - nl * 96;
            size_t off = (size_t)(n0 + nl) * C3 + d;
            Qs[nl][d] = qbase[off];
            Ks[nl][d] = kbase[off];
        }
        __syncthreads();

        if (t < 192) {
            int d = (t < 96) ? t : (t - 96);
#pragma unroll
            for (int nl = 0; nl < 16; nl++) {
                float v = (t < 96) ? Qs[nl][d] : Ks[nl][d];
                nss += v * v;
            }
        }
#pragma unroll
        for (int nl = 0; nl < 16; nl++) {
            const float2* qr = (const float2*)&Qs[nl][ty * 6];
            const float2* kr = (const float2*)&Ks[nl][tx * 6];
            float2 a01 = qr[0], a23 = qr[1], a45 = qr[2];
            float2 c01 = kr[0], c23 = kr[1], c45 = kr[2];
            float a[6] = {a01.x, a01.y, a23.x, a23.y, a45.x, a45.y};
            float cc[6] = {c01.x, c01.y, c23.x, c23.y, c45.x, c45.y};
#pragma unroll
            for (int i = 0; i < 6; i++)
#pragma unroll
                for (int j = 0; j < 6; j++) acc[i][j] += a[i] * cc[j];
        }
        __syncthreads();
    }

    float* G = g_gram + bh * HD * HD;
#pragma unroll
    for (int i = 0; i < 6; i++)
#pragma unroll
        for (int j = 0; j < 6; j++)
            atomicAdd(&G[(ty * 6 + i) * HD + tx * 6 + j], acc[i][j]);

    if (t < 96)       atomicAdd(&g_qss[bh * HD + t], nss);
    else if (t < 192) atomicAdd(&g_kss[bh * HD + (t - 96)], nss);
}

// ---------------------------------------------------------------------------
// Softmax with folded norms + temperature
// ---------------------------------------------------------------------------
__global__ void softmax_kernel(const float* __restrict__ temperature) {
    const int bh = blockIdx.x;
    const int h  = bh & 7;
    const int t  = threadIdx.x;

    __shared__ float invk[96];
    __shared__ float invq[96];
    if (t < 96) {
        invq[t] = 1.0f / fmaxf(sqrtf(g_qss[bh * HD + t]), 1e-12f);
        invk[t] = 1.0f / fmaxf(sqrtf(g_kss[bh * HD + t]), 1e-12f);
    }
    __syncthreads();

    if (t < 96) {
        const float tmp = temperature[h];
        const float* Grow = g_gram + bh * HD * HD + t * HD;
        float* Arow       = g_attn + bh * HD * HD + t * HD;
        const float sd = tmp * invq[t];

        float m = -1e30f;
        for (int e = 0; e < 96; e++) {
            float v = Grow[e] * sd * invk[e];
            m = fmaxf(m, v);
        }
        float sum = 0.0f;
        for (int e = 0; e < 96; e++) {
            float v = expf(Grow[e] * sd * invk[e] - m);
            Arow[e] = v;
            sum += v;
        }
        const float inv = 1.0f / sum;
        for (int e = 0; e < 96; e++) Arow[e] *= inv;
    }
}

// ---------------------------------------------------------------------------
// attn @ v -> ctx (bf16 hi/lo split, [B,N,C] layout), float4 smem reads
// ---------------------------------------------------------------------------
__global__ __launch_bounds__(256) void av_kernel() {
    const int bh    = blockIdx.x;
    const int chunk = blockIdx.y;
    const int b = bh >> 3, h = bh & 7;

    __shared__ __align__(16) float At[96][100];
    __shared__ __align__(16) float Vs[16][100];

    const int t  = threadIdx.x;
    const int tx = t & 15, ty = t >> 4;

    for (int i = t; i < HD * HD; i += 256) {
        int d = i / 96, e = i - d * 96;
        At[d][e] = g_attn[bh * HD * HD + i];
    }

    const float* vbase = g_qkv + (size_t)b * NN * C3 + 2 * CC + h * HD;
    __nv_bfloat16* ohbase = g_chi + (size_t)b * NN * CC + h * HD;
    __nv_bfloat16* olbase = g_clo + (size_t)b * NN * CC + h * HD;

    const int nstart = chunk * 256;
    for (int n0 = nstart; n0 < nstart + 256; n0 += 16) {
        for (int i = t; i < 16 * 96; i += 256) {
            int nl = i / 96, e = i - nl * 96;
            Vs[nl][e] = vbase[(size_t)(n0 + nl) * C3 + e];
        }
        __syncthreads();

        float acc[6];
#pragma unroll
        for (int i = 0; i < 6; i++) acc[i] = 0.0f;
#pragma unroll
        for (int e4 = 0; e4 < 24; e4++) {
            float4 v = *(const float4*)&Vs[tx][e4 * 4];
#pragma unroll
            for (int i = 0; i < 6; i++) {
                float4 a = *(const float4*)&At[ty * 6 + i][e4 * 4];
                acc[i] += a.x * v.x + a.y * v.y + a.z * v.z + a.w * v.w;
            }
        }
        size_t ooff = (size_t)(n0 + tx) * CC + ty * 6;
#pragma unroll
        for (int i = 0; i < 6; i++) {
            __nv_bfloat16 hh = __float2bfloat16(acc[i]);
            ohbase[ooff + i] = hh;
            olbase[ooff + i] = __float2bfloat16(acc[i] - __bfloat162float(hh));
        }
        __syncthreads();
    }
}

// ---------------------------------------------------------------------------
extern "C" void kernel_launch(void* const* d_in, const int* in_sizes, int n_in,
                              void* d_out, int out_size)
{
    const float* x     = (const float*)d_in[0];
    const float* Wqkv  = (const float*)d_in[1];
    const float* temp  = (const float*)d_in[2];
    const float* Wproj = (const float*)d_in[3];
    const float* bproj = (const float*)d_in[4];
    float* out = (float*)d_out;

    cudaFuncSetAttribute(gemm_mma, cudaFuncAttributeMaxDynamicSharedMemorySize,
                         GEMM_SMEM_BYTES);

    __nv_bfloat16 *xhi, *xlo, *chi, *clo, *wqh, *wql, *wph, *wpl;
    cudaGetSymbolAddress((void**)&xhi, g_xhi);
    cudaGetSymbolAddress((void**)&xlo, g_xlo);
    cudaGetSymbolAddress((void**)&chi, g_chi);
    cudaGetSymbolAddress((void**)&clo, g_clo);
    cudaGetSymbolAddress((void**)&wqh, g_wq_hi);
    cudaGetSymbolAddress((void**)&wql, g_wq_lo);
    cudaGetSymbolAddress((void**)&wph, g_wp_hi);
    cudaGetSymbolAddress((void**)&wpl, g_wp_lo);
    float* qkv;
    cudaGetSymbolAddress((void**)&qkv, g_qkv);

    // 1) split conversions (coalesced tiled transpose)
    conv_x_kernel<<<1184, 256>>>(x);
    transp_kernel<<<dim3(C3 / 32, CC / 32), 256>>>(Wqkv, wqh, wql, CC, C3);
    transp_kernel<<<dim3(CC / 32, CC / 32), 256>>>(Wproj, wph, wpl, CC, CC);

    // 2) qkv = x @ Wqkv via HMMA (bf16-split, shared-tile 3-term)
    gemm_mma<<<dim3(C3 / 128, BN / 128), 256, GEMM_SMEM_BYTES>>>(
        xhi, xlo, wqh, wql, qkv, nullptr, C3);

    // 3) attention middle
    zero_kernel<<<(BHCNT * HD * HD + 255) / 256, 256>>>();
    gram_kernel<<<dim3(BHCNT, 8), 256>>>();
    softmax_kernel<<<BHCNT, 128>>>(temp);
    av_kernel<<<dim3(BHCNT, 16), 256>>>();

    // 4) out = ctx @ Wproj + bias via HMMA (bf16-split, shared-tile 3-term)
    gemm_mma<<<dim3(CC / 128, BN / 128), 256, GEMM_SMEM_BYTES>>>(
        chi, clo, wph, wpl, out, bproj, CC);
}

// round 12
// speedup vs baseline: 1.4256x; 1.4256x over previous
#include <cuda_runtime.h>
#include <cuda_bf16.h>
#include <math.h>
#include <stdint.h>

// Problem constants
#define BB   8
#define NN   4096
#define CC   768
#define HH   8
#define HD   96
#define BN   32768
#define C3   2304
#define BHCNT 64

// ---------------------------------------------------------------------------
// Scratch (device globals: allocation-free, graph-capturable)
// ---------------------------------------------------------------------------
__device__ float g_qkv[(size_t)BN * C3];               // [bn][3C] fp32 qkv
__device__ __nv_bfloat16 g_xhi[(size_t)BN * CC];       // x split
__device__ __nv_bfloat16 g_xlo[(size_t)BN * CC];
__device__ __nv_bfloat16 g_chi[(size_t)BN * CC];       // ctx split (av output)
__device__ __nv_bfloat16 g_clo[(size_t)BN * CC];
__device__ __nv_bfloat16 g_wq_hi[(size_t)C3 * CC];     // Wqkv^T [2304][768]
__device__ __nv_bfloat16 g_wq_lo[(size_t)C3 * CC];
__device__ __nv_bfloat16 g_wp_hi[(size_t)CC * CC];     // Wproj^T [768][768]
__device__ __nv_bfloat16 g_wp_lo[(size_t)CC * CC];
__device__ float g_gram[BHCNT * HD * HD];
__device__ float g_attn[BHCNT * HD * HD];
__device__ float g_qss[BHCNT * HD];
__device__ float g_kss[BHCNT * HD];

// ---------------------------------------------------------------------------
// Baseline-PTX helpers (sm_80+, no 'a'-gated features)
// ---------------------------------------------------------------------------
__device__ __forceinline__ uint32_t smem_u32(const void* p) {
    uint32_t a;
    asm("{ .reg .u64 t; cvta.to.shared.u64 t, %1; cvt.u32.u64 %0, t; }" : "=r"(a) : "l"(p));
    return a;
}
__device__ __forceinline__ void cp16(uint32_t saddr, const void* g) {
    asm volatile("cp.async.cg.shared.global [%0], [%1], 16;" :: "r"(saddr), "l"(g) : "memory");
}
__device__ __forceinline__ void cp_commit() {
    asm volatile("cp.async.commit_group;" ::: "memory");
}
__device__ __forceinline__ void cp_wait0() {
    asm volatile("cp.async.wait_group 0;" ::: "memory");
}
__device__ __forceinline__ void ldsm4(uint32_t& r0, uint32_t& r1, uint32_t& r2, uint32_t& r3,
                                      uint32_t addr) {
    asm volatile("ldmatrix.sync.aligned.m8n8.x4.shared.b16 {%0,%1,%2,%3}, [%4];"
                 : "=r"(r0), "=r"(r1), "=r"(r2), "=r"(r3) : "r"(addr));
}
__device__ __forceinline__ void mma16816(float* d, const uint32_t* a, const uint32_t* b) {
    asm volatile(
        "mma.sync.aligned.m16n8k16.row.col.f32.bf16.bf16.f32 "
        "{%0,%1,%2,%3}, {%4,%5,%6,%7}, {%8,%9}, {%0,%1,%2,%3};"
        : "+f"(d[0]), "+f"(d[1]), "+f"(d[2]), "+f"(d[3])
        : "r"(a[0]), "r"(a[1]), "r"(a[2]), "r"(a[3]), "r"(b[0]), "r"(b[1]));
}

// ---------------------------------------------------------------------------
// bf16 hi/lo split conversion for x
// ---------------------------------------------------------------------------
__global__ void conv_x_kernel(const float* __restrict__ x) {
    size_t i = (size_t)blockIdx.x * 256 + threadIdx.x;
    const size_t total = (size_t)BN * CC / 4;
    for (; i < total; i += (size_t)gridDim.x * 256) {
        float4 v = ((const float4*)x)[i];
        __nv_bfloat16 h0 = __float2bfloat16(v.x), h1 = __float2bfloat16(v.y);
        __nv_bfloat16 h2 = __float2bfloat16(v.z), h3 = __float2bfloat16(v.w);
        __nv_bfloat16 l0 = __float2bfloat16(v.x - __bfloat162float(h0));
        __nv_bfloat16 l1 = __float2bfloat16(v.y - __bfloat162float(h1));
        __nv_bfloat16 l2 = __float2bfloat16(v.z - __bfloat162float(h2));
        __nv_bfloat16 l3 = __float2bfloat16(v.w - __bfloat162float(h3));
        g_xhi[i*4+0] = h0; g_xhi[i*4+1] = h1; g_xhi[i*4+2] = h2; g_xhi[i*4+3] = h3;
        g_xlo[i*4+0] = l0; g_xlo[i*4+1] = l1; g_xlo[i*4+2] = l2; g_xlo[i*4+3] = l3;
    }
}

// ---------------------------------------------------------------------------
// Tiled transpose + hi/lo split: out[n][k] = W[k][n], W is [K][Nn].
// 32x32 tiles, coalesced on both sides. grid (Nn/32, K/32), 256 threads.
// ---------------------------------------------------------------------------
__global__ __launch_bounds__(256) void transp_kernel(
    const float* __restrict__ W,
    __nv_bfloat16* __restrict__ Thi, __nv_bfloat16* __restrict__ Tlo,
    int K, int Nn)
{
    __shared__ float sm[32][33];
    const int n0 = blockIdx.x * 32, k0 = blockIdx.y * 32;
    const int c = threadIdx.x & 31, r = threadIdx.x >> 5;   // 8 row-groups

#pragma unroll
    for (int rr = 0; rr < 4; rr++)
        sm[r + rr * 8][c] = W[(size_t)(k0 + r + rr * 8) * Nn + n0 + c];
    __syncthreads();

#pragma unroll
    for (int rr = 0; rr < 4; rr++) {
        const int n = n0 + r + rr * 8;
        const float v = sm[c][r + rr * 8];
        __nv_bfloat16 h = __float2bfloat16(v);
        Thi[(size_t)n * K + k0 + c] = h;
        Tlo[(size_t)n * K + k0 + c] = __float2bfloat16(v - __bfloat162float(h));
    }
}

// ---------------------------------------------------------------------------
// HMMA bf16-split GEMM (R7-proven structure): C[m][n] = sum_k A[m][k]*B[n][k]
// 3 sequential passes folded into chunk loop: hi*hi + hi*lo + lo*hi.
// CTA tile 128x128, 8 warps of 64x32; K-chunk 64; cp.async double buffer.
// SMEM: 2 stages x (A 16KB + B 16KB) = 64KB. No occupancy clamp.
// ---------------------------------------------------------------------------
#define GEMM_SMEM_BYTES 65536
#define NCHUNK 36     // 12 k-chunks x 3 split passes

__global__ __launch_bounds__(256) void gemm_mma(
    const __nv_bfloat16* __restrict__ Ahi, const __nv_bfloat16* __restrict__ Alo,
    const __nv_bfloat16* __restrict__ Bhi, const __nv_bfloat16* __restrict__ Blo,
    float* __restrict__ C, const float* __restrict__ bias, int ldc)
{
    extern __shared__ char smem[];
    const uint32_t sb = smem_u32(smem);
    const int t = threadIdx.x;
    const int lane = t & 31, wid = t >> 5;
    const int m0 = blockIdx.y * 128;
    const int n0 = blockIdx.x * 128;
    const int wm = (wid & 1) * 64;       // warp m-offset
    const int wn = (wid >> 1) * 32;      // warp n-offset

    // --- loader precompute: 4 x 16B for A and for B per thread per chunk ---
    int lso[4], lgo[4];
#pragma unroll
    for (int i = 0; i < 4; i++) {
        int idx = t + 256 * i, row = idx >> 3, seg = idx & 7;
        lso[i] = row * 128 + ((seg * 16) ^ ((row & 7) << 4));  // swizzled smem off
        lgo[i] = row * CC + seg * 8;                           // gmem elem off
    }

    // --- compute precompute (ldmatrix lane addressing) ---
    const int q = lane >> 3, r = lane & 7;
    const uint32_t rx = (uint32_t)(r << 4);
    const int aro = r + (q & 1) * 8;      // A row-in-tile
    const int akb = (q >> 1) * 16;        // A k-half byte offset
    const int bro = r + (q >> 1) * 8;     // B row-in-tile
    const int bkb = (q & 1) * 16;         // B k-half byte offset
    uint32_t Ab[2][4], Bb[2][2];
#pragma unroll
    for (int s = 0; s < 2; s++) {
#pragma unroll
        for (int mt = 0; mt < 4; mt++)
            Ab[s][mt] = sb + s * 32768u + (uint32_t)(wm + mt * 16 + aro) * 128u;
#pragma unroll
        for (int n2 = 0; n2 < 2; n2++)
            Bb[s][n2] = sb + s * 32768u + 16384u + (uint32_t)(wn + n2 * 16 + bro) * 128u;
    }

    float acc[4][4][4];
#pragma unroll
    for (int mt = 0; mt < 4; mt++)
#pragma unroll
        for (int nt = 0; nt < 4; nt++)
#pragma unroll
            for (int i = 0; i < 4; i++) acc[mt][nt][i] = 0.0f;

    // --- preload chunk 0 (pass 0: hi*hi, k0 = 0) ---
#pragma unroll
    for (int i = 0; i < 4; i++) {
        cp16(sb + lso[i],          Ahi + (size_t)m0 * CC + lgo[i]);
        cp16(sb + 16384u + lso[i], Bhi + (size_t)n0 * CC + lgo[i]);
    }
    cp_commit();
    cp_wait0();
    __syncthreads();

    for (int c = 0; c < NCHUNK; c++) {
        const int s = c & 1;
        if (c + 1 < NCHUNK) {
            const int pn = c + 1;
            const int pass = pn / 12;
            const int k0 = (pn - pass * 12) * 64;
            const __nv_bfloat16* Ap = (pass == 2) ? Alo : Ahi;
            const __nv_bfloat16* Bp = (pass == 1) ? Blo : Bhi;
            const uint32_t st = sb + (uint32_t)((c + 1) & 1) * 32768u;
#pragma unroll
            for (int i = 0; i < 4; i++) {
                cp16(st + lso[i],          Ap + (size_t)m0 * CC + k0 + lgo[i]);
                cp16(st + 16384u + lso[i], Bp + (size_t)n0 * CC + k0 + lgo[i]);
            }
            cp_commit();
        }

        // compute on stage s: 4 k16 steps
#pragma unroll
        for (int kk = 0; kk < 4; kk++) {
            const uint32_t ak = ((uint32_t)(kk * 32 + akb)) ^ rx;
            const uint32_t bk = ((uint32_t)(kk * 32 + bkb)) ^ rx;
            uint32_t a[4][4];
#pragma unroll
            for (int mt = 0; mt < 4; mt++)
                ldsm4(a[mt][0], a[mt][1], a[mt][2], a[mt][3], Ab[s][mt] + ak);
            uint32_t bfr[4][2];
#pragma unroll
            for (int n2 = 0; n2 < 2; n2++) {
                uint32_t r0, r1, r2, r3;
                ldsm4(r0, r1, r2, r3, Bb[s][n2] + bk);
                bfr[n2 * 2][0] = r0;     bfr[n2 * 2][1] = r1;
                bfr[n2 * 2 + 1][0] = r2; bfr[n2 * 2 + 1][1] = r3;
            }
#pragma unroll
            for (int nt = 0; nt < 4; nt++)
#pragma unroll
                for (int mt = 0; mt < 4; mt++)
                    mma16816(acc[mt][nt], a[mt], bfr[nt]);
        }

        if (c + 1 < NCHUNK) {
            cp_wait0();
            __syncthreads();
        }
    }

    // --- epilogue: direct global stores of D fragments ---
    const int mrow = lane >> 2;
    const int ncol = (lane & 3) * 2;
#pragma unroll
    for (int nt = 0; nt < 4; nt++) {
        const int col = n0 + wn + nt * 8 + ncol;
        float b0 = 0.0f, b1 = 0.0f;
        if (bias != nullptr) { b0 = bias[col]; b1 = bias[col + 1]; }
#pragma unroll
        for (int mt = 0; mt < 4; mt++) {
            const int m = m0 + wm + mt * 16 + mrow;
            float2 v0 = make_float2(acc[mt][nt][0] + b0, acc[mt][nt][1] + b1);
            float2 v1 = make_float2(acc[mt][nt][2] + b0, acc[mt][nt][3] + b1);
            *(float2*)(C + (size_t)m * ldc + col) = v0;
            *(float2*)(C + (size_t)(m + 8) * ldc + col) = v1;
        }
    }
}

// ---------------------------------------------------------------------------
// Zero reduction scratch
// ---------------------------------------------------------------------------
__global__ void zero_kernel() {
    int i = blockIdx.x * 256 + threadIdx.x;
    if (i < BHCNT * HD * HD) g_gram[i] = 0.0f;
    if (i < BHCNT * HD) { g_qss[i] = 0.0f; g_kss[i] = 0.0f; }
}

// ---------------------------------------------------------------------------
// Split-K Gram + norms (float2-vectorized smem reads)
// ---------------------------------------------------------------------------
__global__ __launch_bounds__(256) void gram_kernel() {
    const int bh = blockIdx.x;
    const int s  = blockIdx.y;
    const int b  = bh >> 3, h = bh & 7;
    const int NSPLIT = NN / 8;
    const int nbase = s * NSPLIT;

    __shared__ __align__(16) float Qs[16][96];
    __shared__ __align__(16) float Ks[16][96];

    const int t  = threadIdx.x;
    const int tx = t & 15, ty = t >> 4;

    float acc[6][6];
#pragma unroll
    for (int i = 0; i < 6; i++)
#pragma unroll
        for (int j = 0; j < 6; j++) acc[i][j] = 0.0f;
    float nss = 0.0f;

    const float* qbase = g_qkv + (size_t)b * NN * C3 + h * HD;
    const float* kbase = qbase + CC;

    for (int n0 = nbase; n0 < nbase + NSPLIT; n0 += 16) {
        for (int i = t; i < 16 * 96; i += 256) {
            int nl = i / 96, d = i - nl * 96;
            size_t off = (size_t)(n0 + nl) * C3 + d;
            Qs[nl][d] = qbase[off];
            Ks[nl][d] = kbase[off];
        }
        __syncthreads();

        if (t < 192) {
            int d = (t < 96) ? t : (t - 96);
#pragma unroll
            for (int nl = 0; nl < 16; nl++) {
                float v = (t < 96) ? Qs[nl][d] : Ks[nl][d];
                nss += v * v;
            }
        }
#pragma unroll
        for (int nl = 0; nl < 16; nl++) {
            const float2* qr = (const float2*)&Qs[nl][ty * 6];
            const float2* kr = (const float2*)&Ks[nl][tx * 6];
            float2 a01 = qr[0], a23 = qr[1], a45 = qr[2];
            float2 c01 = kr[0], c23 = kr[1], c45 = kr[2];
            float a[6] = {a01.x, a01.y, a23.x, a23.y, a45.x, a45.y};
            float cc[6] = {c01.x, c01.y, c23.x, c23.y, c45.x, c45.y};
#pragma unroll
            for (int i = 0; i < 6; i++)
#pragma unroll
                for (int j = 0; j < 6; j++) acc[i][j] += a[i] * cc[j];
        }
        __syncthreads();
    }

    float* G = g_gram + bh * HD * HD;
#pragma unroll
    for (int i = 0; i < 6; i++)
#pragma unroll
        for (int j = 0; j < 6; j++)
            atomicAdd(&G[(ty * 6 + i) * HD + tx * 6 + j], acc[i][j]);

    if (t < 96)       atomicAdd(&g_qss[bh * HD + t], nss);
    else if (t < 192) atomicAdd(&g_kss[bh * HD + (t - 96)], nss);
}

// ---------------------------------------------------------------------------
// Softmax with folded norms + temperature
// ---------------------------------------------------------------------------
__global__ void softmax_kernel(const float* __restrict__ temperature) {
    const int bh = blockIdx.x;
    const int h  = bh & 7;
    const int t  = threadIdx.x;

    __shared__ float invk[96];
    __shared__ float invq[96];
    if (t < 96) {
        invq[t] = 1.0f / fmaxf(sqrtf(g_qss[bh * HD + t]), 1e-12f);
        invk[t] = 1.0f / fmaxf(sqrtf(g_kss[bh * HD + t]), 1e-12f);
    }
    __syncthreads();

    if (t < 96) {
        const float tmp = temperature[h];
        const float* Grow = g_gram + bh * HD * HD + t * HD;
        float* Arow       = g_attn + bh * HD * HD + t * HD;
        const float sd = tmp * invq[t];

        float m = -1e30f;
        for (int e = 0; e < 96; e++) {
            float v = Grow[e] * sd * invk[e];
            m = fmaxf(m, v);
        }
        float sum = 0.0f;
        for (int e = 0; e < 96; e++) {
            float v = expf(Grow[e] * sd * invk[e] - m);
            Arow[e] = v;
            sum += v;
        }
        const float inv = 1.0f / sum;
        for (int e = 0; e < 96; e++) Arow[e] *= inv;
    }
}

// ---------------------------------------------------------------------------
// attn @ v -> ctx (bf16 hi/lo split, [B,N,C] layout), float4 smem reads
// ---------------------------------------------------------------------------
__global__ __launch_bounds__(256) void av_kernel() {
    const int bh    = blockIdx.x;
    const int chunk = blockIdx.y;
    const int b = bh >> 3, h = bh & 7;

    __shared__ __align__(16) float At[96][100];
    __shared__ __align__(16) float Vs[16][100];

    const int t  = threadIdx.x;
    const int tx = t & 15, ty = t >> 4;

    for (int i = t; i < HD * HD; i += 256) {
        int d = i / 96, e = i - d * 96;
        At[d][e] = g_attn[bh * HD * HD + i];
    }

    const float* vbase = g_qkv + (size_t)b * NN * C3 + 2 * CC + h * HD;
    __nv_bfloat16* ohbase = g_chi + (size_t)b * NN * CC + h * HD;
    __nv_bfloat16* olbase = g_clo + (size_t)b * NN * CC + h * HD;

    const int nstart = chunk * 256;
    for (int n0 = nstart; n0 < nstart + 256; n0 += 16) {
        for (int i = t; i < 16 * 96; i += 256) {
            int nl = i / 96, e = i - nl * 96;
            Vs[nl][e] = vbase[(size_t)(n0 + nl) * C3 + e];
        }
        __syncthreads();

        float acc[6];
#pragma unroll
        for (int i = 0; i < 6; i++) acc[i] = 0.0f;
#pragma unroll
        for (int e4 = 0; e4 < 24; e4++) {
            float4 v = *(const float4*)&Vs[tx][e4 * 4];
#pragma unroll
            for (int i = 0; i < 6; i++) {
                float4 a = *(const float4*)&At[ty * 6 + i][e4 * 4];
                acc[i] += a.x * v.x + a.y * v.y + a.z * v.z + a.w * v.w;
            }
        }
        size_t ooff = (size_t)(n0 + tx) * CC + ty * 6;
#pragma unroll
        for (int i = 0; i < 6; i++) {
            __nv_bfloat16 hh = __float2bfloat16(acc[i]);
            ohbase[ooff + i] = hh;
            olbase[ooff + i] = __float2bfloat16(acc[i] - __bfloat162float(hh));
        }
        __syncthreads();
    }
}

// ---------------------------------------------------------------------------
extern "C" void kernel_launch(void* const* d_in, const int* in_sizes, int n_in,
                              void* d_out, int out_size)
{
    const float* x     = (const float*)d_in[0];
    const float* Wqkv  = (const float*)d_in[1];
    const float* temp  = (const float*)d_in[2];
    const float* Wproj = (const float*)d_in[3];
    const float* bproj = (const float*)d_in[4];
    float* out = (float*)d_out;

    cudaFuncSetAttribute(gemm_mma, cudaFuncAttributeMaxDynamicSharedMemorySize,
                         GEMM_SMEM_BYTES);

    __nv_bfloat16 *xhi, *xlo, *chi, *clo, *wqh, *wql, *wph, *wpl;
    cudaGetSymbolAddress((void**)&xhi, g_xhi);
    cudaGetSymbolAddress((void**)&xlo, g_xlo);
    cudaGetSymbolAddress((void**)&chi, g_chi);
    cudaGetSymbolAddress((void**)&clo, g_clo);
    cudaGetSymbolAddress((void**)&wqh, g_wq_hi);
    cudaGetSymbolAddress((void**)&wql, g_wq_lo);
    cudaGetSymbolAddress((void**)&wph, g_wp_hi);
    cudaGetSymbolAddress((void**)&wpl, g_wp_lo);
    float* qkv;
    cudaGetSymbolAddress((void**)&qkv, g_qkv);

    // 1) split conversions (coalesced tiled transpose)
    conv_x_kernel<<<1184, 256>>>(x);
    transp_kernel<<<dim3(C3 / 32, CC / 32), 256>>>(Wqkv, wqh, wql, CC, C3);
    transp_kernel<<<dim3(CC / 32, CC / 32), 256>>>(Wproj, wph, wpl, CC, CC);

    // 2) qkv = x @ Wqkv via HMMA (bf16-split, 3-pass, R7 structure)
    gemm_mma<<<dim3(C3 / 128, BN / 128), 256, GEMM_SMEM_BYTES>>>(
        xhi, xlo, wqh, wql, qkv, nullptr, C3);

    // 3) attention middle
    zero_kernel<<<(BHCNT * HD * HD + 255) / 256, 256>>>();
    gram_kernel<<<dim3(BHCNT, 8), 256>>>();
    softmax_kernel<<<BHCNT, 128>>>(temp);
    av_kernel<<<dim3(BHCNT, 16), 256>>>();

    // 4) out = ctx @ Wproj + bias via HMMA (bf16-split, 3-pass, R7 structure)
    gemm_mma<<<dim3(CC / 128, BN / 128), 256, GEMM_SMEM_BYTES>>>(
        chi, clo, wph, wpl, out, bproj, CC);
}

// round 13
// speedup vs baseline: 1.6568x; 1.1622x over previous
#include <cuda_runtime.h>
#include <cuda_bf16.h>
#include <math.h>
#include <stdint.h>

// Problem constants
#define BB   8
#define NN   4096
#define CC   768
#define HH   8
#define HD   96
#define BN   32768
#define C3   2304
#define BHCNT 64

// ---------------------------------------------------------------------------
// Scratch (device globals: allocation-free, graph-capturable)
// ---------------------------------------------------------------------------
__device__ float g_qkv[(size_t)BN * C3];               // [bn][3C] fp32 qkv
__device__ __nv_bfloat16 g_xhi[(size_t)BN * CC];       // x split
__device__ __nv_bfloat16 g_xlo[(size_t)BN * CC];
__device__ __nv_bfloat16 g_chi[(size_t)BN * CC];       // ctx split (av output)
__device__ __nv_bfloat16 g_clo[(size_t)BN * CC];
__device__ __nv_bfloat16 g_wq_hi[(size_t)C3 * CC];     // Wqkv^T [2304][768]
__device__ __nv_bfloat16 g_wq_lo[(size_t)C3 * CC];
__device__ __nv_bfloat16 g_wp_hi[(size_t)CC * CC];     // Wproj^T [768][768]
__device__ __nv_bfloat16 g_wp_lo[(size_t)CC * CC];
__device__ float g_gram[BHCNT * HD * HD];
__device__ float g_attn[BHCNT * HD * HD];
__device__ float g_qss[BHCNT * HD];
__device__ float g_kss[BHCNT * HD];

// ---------------------------------------------------------------------------
// Baseline-PTX helpers (sm_80+, no 'a'-gated features)
// ---------------------------------------------------------------------------
__device__ __forceinline__ uint32_t smem_u32(const void* p) {
    uint32_t a;
    asm("{ .reg .u64 t; cvta.to.shared.u64 t, %1; cvt.u32.u64 %0, t; }" : "=r"(a) : "l"(p));
    return a;
}
__device__ __forceinline__ void cp16(uint32_t saddr, const void* g) {
    asm volatile("cp.async.cg.shared.global [%0], [%1], 16;" :: "r"(saddr), "l"(g) : "memory");
}
__device__ __forceinline__ void cp_commit() {
    asm volatile("cp.async.commit_group;" ::: "memory");
}
__device__ __forceinline__ void ldsm4(uint32_t& r0, uint32_t& r1, uint32_t& r2, uint32_t& r3,
                                      uint32_t addr) {
    asm volatile("ldmatrix.sync.aligned.m8n8.x4.shared.b16 {%0,%1,%2,%3}, [%4];"
                 : "=r"(r0), "=r"(r1), "=r"(r2), "=r"(r3) : "r"(addr));
}
__device__ __forceinline__ void mma16816(float* d, const uint32_t* a, const uint32_t* b) {
    asm volatile(
        "mma.sync.aligned.m16n8k16.row.col.f32.bf16.bf16.f32 "
        "{%0,%1,%2,%3}, {%4,%5,%6,%7}, {%8,%9}, {%0,%1,%2,%3};"
        : "+f"(d[0]), "+f"(d[1]), "+f"(d[2]), "+f"(d[3])
        : "r"(a[0]), "r"(a[1]), "r"(a[2]), "r"(a[3]), "r"(b[0]), "r"(b[1]));
}
__device__ __forceinline__ uint32_t pk(__nv_bfloat16 a, __nv_bfloat16 b) {
    __nv_bfloat162 t = __halves2bfloat162(a, b);
    return *reinterpret_cast<uint32_t*>(&t);
}

// ---------------------------------------------------------------------------
// bf16 hi/lo split conversion for x (packed uint2 stores)
// ---------------------------------------------------------------------------
__global__ void conv_x_kernel(const float* __restrict__ x) {
    size_t i = (size_t)blockIdx.x * 256 + threadIdx.x;
    const size_t total = (size_t)BN * CC / 4;
    for (; i < total; i += (size_t)gridDim.x * 256) {
        float4 v = ((const float4*)x)[i];
        __nv_bfloat16 h0 = __float2bfloat16(v.x), h1 = __float2bfloat16(v.y);
        __nv_bfloat16 h2 = __float2bfloat16(v.z), h3 = __float2bfloat16(v.w);
        __nv_bfloat16 l0 = __float2bfloat16(v.x - __bfloat162float(h0));
        __nv_bfloat16 l1 = __float2bfloat16(v.y - __bfloat162float(h1));
        __nv_bfloat16 l2 = __float2bfloat16(v.z - __bfloat162float(h2));
        __nv_bfloat16 l3 = __float2bfloat16(v.w - __bfloat162float(h3));
        ((uint2*)g_xhi)[i] = make_uint2(pk(h0, h1), pk(h2, h3));
        ((uint2*)g_xlo)[i] = make_uint2(pk(l0, l1), pk(l2, l3));
    }
}

// ---------------------------------------------------------------------------
// Tiled transpose + hi/lo split: out[n][k] = W[k][n], W is [K][Nn].
// ---------------------------------------------------------------------------
__global__ __launch_bounds__(256) void transp_kernel(
    const float* __restrict__ W,
    __nv_bfloat16* __restrict__ Thi, __nv_bfloat16* __restrict__ Tlo,
    int K, int Nn)
{
    __shared__ float sm[32][33];
    const int n0 = blockIdx.x * 32, k0 = blockIdx.y * 32;
    const int c = threadIdx.x & 31, r = threadIdx.x >> 5;   // 8 row-groups

#pragma unroll
    for (int rr = 0; rr < 4; rr++)
        sm[r + rr * 8][c] = W[(size_t)(k0 + r + rr * 8) * Nn + n0 + c];
    __syncthreads();

#pragma unroll
    for (int rr = 0; rr < 4; rr++) {
        const int n = n0 + r + rr * 8;
        const float v = sm[c][r + rr * 8];
        __nv_bfloat16 h = __float2bfloat16(v);
        Thi[(size_t)n * K + k0 + c] = h;
        Tlo[(size_t)n * K + k0 + c] = __float2bfloat16(v - __bfloat162float(h));
    }
}

// ---------------------------------------------------------------------------
// HMMA bf16-split GEMM, 3-stage cp.async pipeline.
// C[m][n] = sum_k A[m][k]*B[n][k]; 3 passes: hi*hi + hi*lo + lo*hi.
// CTA tile 128x128, 8 warps of 64x32; K-chunk 64.
// SMEM: 3 stages x (A 16KB + B 16KB) = 96KB. 2 CTAs/SM.
// ---------------------------------------------------------------------------
#define GEMM_SMEM_BYTES 98304
#define NCHUNK 36     // 12 k-chunks x 3 split passes

__global__ __launch_bounds__(256) void gemm_mma(
    const __nv_bfloat16* __restrict__ Ahi, const __nv_bfloat16* __restrict__ Alo,
    const __nv_bfloat16* __restrict__ Bhi, const __nv_bfloat16* __restrict__ Blo,
    float* __restrict__ C, const float* __restrict__ bias, int ldc)
{
    extern __shared__ char smem[];
    const uint32_t sb = smem_u32(smem);
    const int t = threadIdx.x;
    const int lane = t & 31, wid = t >> 5;
    const int m0 = blockIdx.y * 128;
    const int n0 = blockIdx.x * 128;
    const int wm = (wid & 1) * 64;       // warp m-offset
    const int wn = (wid >> 1) * 32;      // warp n-offset

    // loader precompute: 4 x 16B for A and B per thread per chunk
    int lso[4], lgo[4];
#pragma unroll
    for (int i = 0; i < 4; i++) {
        int idx = t + 256 * i, row = idx >> 3, seg = idx & 7;
        lso[i] = row * 128 + ((seg * 16) ^ ((row & 7) << 4));  // swizzled smem off
        lgo[i] = row * CC + seg * 8;                           // gmem elem off
    }

    // ldmatrix lane addressing (stage-0 bases; stage offset added at use)
    const int q = lane >> 3, r = lane & 7;
    const uint32_t rx = (uint32_t)(r << 4);
    const int aro = r + (q & 1) * 8;
    const int akb = (q >> 1) * 16;
    const int bro = r + (q >> 1) * 8;
    const int bkb = (q & 1) * 16;
    uint32_t Ab0[4], Bb0[2];
#pragma unroll
    for (int mt = 0; mt < 4; mt++)
        Ab0[mt] = sb + (uint32_t)(wm + mt * 16 + aro) * 128u;
#pragma unroll
    for (int n2 = 0; n2 < 2; n2++)
        Bb0[n2] = sb + 16384u + (uint32_t)(wn + n2 * 16 + bro) * 128u;

    float acc[4][4][4];
#pragma unroll
    for (int mt = 0; mt < 4; mt++)
#pragma unroll
        for (int nt = 0; nt < 4; nt++)
#pragma unroll
            for (int i = 0; i < 4; i++) acc[mt][nt][i] = 0.0f;

    // --- prologue: preload chunks 0 (stage 0) and 1 (stage 1), pass 0 ---
#pragma unroll
    for (int i = 0; i < 4; i++) {
        cp16(sb + lso[i],          Ahi + (size_t)m0 * CC + lgo[i]);
        cp16(sb + 16384u + lso[i], Bhi + (size_t)n0 * CC + lgo[i]);
    }
    cp_commit();
#pragma unroll
    for (int i = 0; i < 4; i++) {
        cp16(sb + 32768u + lso[i],          Ahi + (size_t)m0 * CC + 64 + lgo[i]);
        cp16(sb + 32768u + 16384u + lso[i], Bhi + (size_t)n0 * CC + 64 + lgo[i]);
    }
    cp_commit();

    int s = 0;   // stage of chunk c
    for (int c = 0; c < NCHUNK; c++) {
        if (c + 1 < NCHUNK) {
            asm volatile("cp.async.wait_group 1;" ::: "memory");
        } else {
            asm volatile("cp.async.wait_group 0;" ::: "memory");
        }
        __syncthreads();

        // issue prefetch of chunk c+2 into stage (s+2)%3 (its last reader,
        // compute(c-1), finished before the barrier above)
        if (c + 2 < NCHUNK) {
            const int pn = c + 2;
            const int pass = pn / 12;
            const int k0 = (pn - pass * 12) * 64;
            const __nv_bfloat16* Ap = (pass == 2) ? Alo : Ahi;
            const __nv_bfloat16* Bp = (pass == 1) ? Blo : Bhi;
            const int s2 = (s + 2 >= 3) ? (s - 1) : (s + 2);
            const uint32_t st = sb + (uint32_t)s2 * 32768u;
#pragma unroll
            for (int i = 0; i < 4; i++) {
                cp16(st + lso[i],          Ap + (size_t)m0 * CC + k0 + lgo[i]);
                cp16(st + 16384u + lso[i], Bp + (size_t)n0 * CC + k0 + lgo[i]);
            }
            cp_commit();
        }

        // compute on stage s: 4 k16 steps
        const uint32_t so = (uint32_t)s * 32768u;
#pragma unroll
        for (int kk = 0; kk < 4; kk++) {
            const uint32_t ak = so + (((uint32_t)(kk * 32 + akb)) ^ rx);
            const uint32_t bk = so + (((uint32_t)(kk * 32 + bkb)) ^ rx);
            uint32_t a[4][4];
#pragma unroll
            for (int mt = 0; mt < 4; mt++)
                ldsm4(a[mt][0], a[mt][1], a[mt][2], a[mt][3], Ab0[mt] + ak);
            uint32_t bfr[4][2];
#pragma unroll
            for (int n2 = 0; n2 < 2; n2++) {
                uint32_t r0, r1, r2, r3;
                ldsm4(r0, r1, r2, r3, Bb0[n2] + bk);
                bfr[n2 * 2][0] = r0;     bfr[n2 * 2][1] = r1;
                bfr[n2 * 2 + 1][0] = r2; bfr[n2 * 2 + 1][1] = r3;
            }
#pragma unroll
            for (int nt = 0; nt < 4; nt++)
#pragma unroll
                for (int mt = 0; mt < 4; mt++)
                    mma16816(acc[mt][nt], a[mt], bfr[nt]);
        }

        s = (s == 2) ? 0 : (s + 1);
    }

    // --- epilogue: direct global stores of D fragments ---
    const int mrow = lane >> 2;
    const int ncol = (lane & 3) * 2;
#pragma unroll
    for (int nt = 0; nt < 4; nt++) {
        const int col = n0 + wn + nt * 8 + ncol;
        float b0 = 0.0f, b1 = 0.0f;
        if (bias != nullptr) { b0 = bias[col]; b1 = bias[col + 1]; }
#pragma unroll
        for (int mt = 0; mt < 4; mt++) {
            const int m = m0 + wm + mt * 16 + mrow;
            float2 v0 = make_float2(acc[mt][nt][0] + b0, acc[mt][nt][1] + b1);
            float2 v1 = make_float2(acc[mt][nt][2] + b0, acc[mt][nt][3] + b1);
            *(float2*)(C + (size_t)m * ldc + col) = v0;
            *(float2*)(C + (size_t)(m + 8) * ldc + col) = v1;
        }
    }
}

// ---------------------------------------------------------------------------
// Zero reduction scratch
// ---------------------------------------------------------------------------
__global__ void zero_kernel() {
    int i = blockIdx.x * 256 + threadIdx.x;
    if (i < BHCNT * HD * HD) g_gram[i] = 0.0f;
    if (i < BHCNT * HD) { g_qss[i] = 0.0f; g_kss[i] = 0.0f; }
}

// ---------------------------------------------------------------------------
// Split-K Gram + norms (16-way split over N)
// ---------------------------------------------------------------------------
__global__ __launch_bounds__(256) void gram_kernel() {
    const int bh = blockIdx.x;
    const int s  = blockIdx.y;
    const int b  = bh >> 3, h = bh & 7;
    const int NSPLIT = NN / 16;      // 256 tokens per split
    const int nbase = s * NSPLIT;

    __shared__ __align__(16) float Qs[16][96];
    __shared__ __align__(16) float Ks[16][96];

    const int t  = threadIdx.x;
    const int tx = t & 15, ty = t >> 4;

    float acc[6][6];
#pragma unroll
    for (int i = 0; i < 6; i++)
#pragma unroll
        for (int j = 0; j < 6; j++) acc[i][j] = 0.0f;
    float nss = 0.0f;

    const float* qbase = g_qkv + (size_t)b * NN * C3 + h * HD;
    const float* kbase = qbase + CC;

    for (int n0 = nbase; n0 < nbase + NSPLIT; n0 += 16) {
        for (int i = t; i < 16 * 96; i += 256) {
            int nl = i / 96, d = i - nl * 96;
            size_t off = (size_t)(n0 + nl) * C3 + d;
            Qs[nl][d] = qbase[off];
            Ks[nl][d] = kbase[off];
        }
        __syncthreads();

        if (t < 192) {
            int d = (t < 96) ? t : (t - 96);
#pragma unroll
            for (int nl = 0; nl < 16; nl++) {
                float v = (t < 96) ? Qs[nl][d] : Ks[nl][d];
                nss += v * v;
            }
        }
#pragma unroll
        for (int nl = 0; nl < 16; nl++) {
            const float2* qr = (const float2*)&Qs[nl][ty * 6];
            const float2* kr = (const float2*)&Ks[nl][tx * 6];
            float2 a01 = qr[0], a23 = qr[1], a45 = qr[2];
            float2 c01 = kr[0], c23 = kr[1], c45 = kr[2];
            float a[6] = {a01.x, a01.y, a23.x, a23.y, a45.x, a45.y};
            float cc[6] = {c01.x, c01.y, c23.x, c23.y, c45.x, c45.y};
#pragma unroll
            for (int i = 0; i < 6; i++)
#pragma unroll
                for (int j = 0; j < 6; j++) acc[i][j] += a[i] * cc[j];
        }
        __syncthreads();
    }

    float* G = g_gram + bh * HD * HD;
#pragma unroll
    for (int i = 0; i < 6; i++)
#pragma unroll
        for (int j = 0; j < 6; j++)
            atomicAdd(&G[(ty * 6 + i) * HD + tx * 6 + j], acc[i][j]);

    if (t < 96)       atomicAdd(&g_qss[bh * HD + t], nss);
    else if (t < 192) atomicAdd(&g_kss[bh * HD + (t - 96)], nss);
}

// ---------------------------------------------------------------------------
// Softmax with folded norms + temperature
// ---------------------------------------------------------------------------
__global__ void softmax_kernel(const float* __restrict__ temperature) {
    const int bh = blockIdx.x;
    const int h  = bh & 7;
    const int t  = threadIdx.x;

    __shared__ float invk[96];
    __shared__ float invq[96];
    if (t < 96) {
        invq[t] = 1.0f / fmaxf(sqrtf(g_qss[bh * HD + t]), 1e-12f);
        invk[t] = 1.0f / fmaxf(sqrtf(g_kss[bh * HD + t]), 1e-12f);
    }
    __syncthreads();

    if (t < 96) {
        const float tmp = temperature[h];
        const float* Grow = g_gram + bh * HD * HD + t * HD;
        float* Arow       = g_attn + bh * HD * HD + t * HD;
        const float sd = tmp * invq[t];

        float m = -1e30f;
        for (int e = 0; e < 96; e++) {
            float v = Grow[e] * sd * invk[e];
            m = fmaxf(m, v);
        }
        float sum = 0.0f;
        for (int e = 0; e < 96; e++) {
            float v = expf(Grow[e] * sd * invk[e] - m);
            Arow[e] = v;
            sum += v;
        }
        const float inv = 1.0f / sum;
        for (int e = 0; e < 96; e++) Arow[e] *= inv;
    }
}

// ---------------------------------------------------------------------------
// attn @ v -> ctx (bf16 hi/lo split, [B,N,C] layout).
// float4 smem reads; output staged in smem, cooperative uint4 stores.
// ---------------------------------------------------------------------------
__global__ __launch_bounds__(256) void av_kernel() {
    const int bh    = blockIdx.x;
    const int chunk = blockIdx.y;
    const int b = bh >> 3, h = bh & 7;

    __shared__ __align__(16) float At[96][100];
    __shared__ __align__(16) float Vs[16][100];
    __shared__ __align__(16) uint32_t Osh[16][48];   // 16 tokens x 96 bf16 (hi)
    __shared__ __align__(16) uint32_t Osl[16][48];   // (lo)

    const int t  = threadIdx.x;
    const int tx = t & 15, ty = t >> 4;

    for (int i = t; i < HD * HD; i += 256) {
        int d = i / 96, e = i - d * 96;
        At[d][e] = g_attn[bh * HD * HD + i];
    }

    const float* vbase = g_qkv + (size_t)b * NN * C3 + 2 * CC + h * HD;
    __nv_bfloat16* ohbase = g_chi + (size_t)b * NN * CC + h * HD;
    __nv_bfloat16* olbase = g_clo + (size_t)b * NN * CC + h * HD;

    const int nstart = chunk * 256;
    for (int n0 = nstart; n0 < nstart + 256; n0 += 16) {
        for (int i = t; i < 16 * 96; i += 256) {
            int nl = i / 96, e = i - nl * 96;
            Vs[nl][e] = vbase[(size_t)(n0 + nl) * C3 + e];
        }
        __syncthreads();   // Vs ready; prior iteration's Osh/Osl stores done

        float acc[6];
#pragma unroll
        for (int i = 0; i < 6; i++) acc[i] = 0.0f;
#pragma unroll
        for (int e4 = 0; e4 < 24; e4++) {
            float4 v = *(const float4*)&Vs[tx][e4 * 4];
#pragma unroll
            for (int i = 0; i < 6; i++) {
                float4 a = *(const float4*)&At[ty * 6 + i][e4 * 4];
                acc[i] += a.x * v.x + a.y * v.y + a.z * v.z + a.w * v.w;
            }
        }
        __nv_bfloat16 hh[6], ll[6];
#pragma unroll
        for (int i = 0; i < 6; i++) {
            hh[i] = __float2bfloat16(acc[i]);
            ll[i] = __float2bfloat16(acc[i] - __bfloat162float(hh[i]));
        }
        Osh[tx][ty * 3 + 0] = pk(hh[0], hh[1]);
        Osh[tx][ty * 3 + 1] = pk(hh[2], hh[3]);
        Osh[tx][ty * 3 + 2] = pk(hh[4], hh[5]);
        Osl[tx][ty * 3 + 0] = pk(ll[0], ll[1]);
        Osl[tx][ty * 3 + 1] = pk(ll[2], ll[3]);
        Osl[tx][ty * 3 + 2] = pk(ll[4], ll[5]);
        __syncthreads();   // Osh/Osl ready

        if (t < 192) {     // 16 rows x 12 uint4 per array
            const int row = t / 12, seg = t - row * 12;
            uint4 vh = *(const uint4*)&Osh[row][seg * 4];
            uint4 vl = *(const uint4*)&Osl[row][seg * 4];
            ((uint4*)(ohbase + (size_t)(n0 + row) * CC))[seg] = vh;
            ((uint4*)(olbase + (size_t)(n0 + row) * CC))[seg] = vl;
        }
        // no trailing sync needed: next iter writes Vs (disjoint), then syncs
    }
}

// ---------------------------------------------------------------------------
extern "C" void kernel_launch(void* const* d_in, const int* in_sizes, int n_in,
                              void* d_out, int out_size)
{
    const float* x     = (const float*)d_in[0];
    const float* Wqkv  = (const float*)d_in[1];
    const float* temp  = (const float*)d_in[2];
    const float* Wproj = (const float*)d_in[3];
    const float* bproj = (const float*)d_in[4];
    float* out = (float*)d_out;

    cudaFuncSetAttribute(gemm_mma, cudaFuncAttributeMaxDynamicSharedMemorySize,
                         GEMM_SMEM_BYTES);

    __nv_bfloat16 *xhi, *xlo, *chi, *clo, *wqh, *wql, *wph, *wpl;
    cudaGetSymbolAddress((void**)&xhi, g_xhi);
    cudaGetSymbolAddress((void**)&xlo, g_xlo);
    cudaGetSymbolAddress((void**)&chi, g_chi);
    cudaGetSymbolAddress((void**)&clo, g_clo);
    cudaGetSymbolAddress((void**)&wqh, g_wq_hi);
    cudaGetSymbolAddress((void**)&wql, g_wq_lo);
    cudaGetSymbolAddress((void**)&wph, g_wp_hi);
    cudaGetSymbolAddress((void**)&wpl, g_wp_lo);
    float* qkv;
    cudaGetSymbolAddress((void**)&qkv, g_qkv);

    // 1) split conversions
    conv_x_kernel<<<1184, 256>>>(x);
    transp_kernel<<<dim3(C3 / 32, CC / 32), 256>>>(Wqkv, wqh, wql, CC, C3);
    transp_kernel<<<dim3(CC / 32, CC / 32), 256>>>(Wproj, wph, wpl, CC, CC);

    // 2) qkv = x @ Wqkv via HMMA (bf16-split, 3-pass, 3-stage pipeline)
    gemm_mma<<<dim3(C3 / 128, BN / 128), 256, GEMM_SMEM_BYTES>>>(
        xhi, xlo, wqh, wql, qkv, nullptr, C3);

    // 3) attention middle
    zero_kernel<<<(BHCNT * HD * HD + 255) / 256, 256>>>();
    gram_kernel<<<dim3(BHCNT, 16), 256>>>();
    softmax_kernel<<<BHCNT, 128>>>(temp);
    av_kernel<<<dim3(BHCNT, 16), 256>>>();

    // 4) out = ctx @ Wproj + bias via HMMA (bf16-split, 3-pass, 3-stage pipeline)
    gemm_mma<<<dim3(CC / 128, BN / 128), 256, GEMM_SMEM_BYTES>>>(
        chi, clo, wph, wpl, out, bproj, CC);
}

// round 14
// speedup vs baseline: 2.1107x; 1.2740x over previous
#include <cuda_runtime.h>
#include <cuda_bf16.h>
#include <math.h>
#include <stdint.h>

// Problem constants
#define BB   8
#define NN   4096
#define CC   768
#define HH   8
#define HD   96
#define BN   32768
#define C3   2304
#define BHCNT 64

// ---------------------------------------------------------------------------
// Scratch (device globals: allocation-free, graph-capturable)
// ---------------------------------------------------------------------------
__device__ __nv_bfloat16 g_qkvh[(size_t)BN * C3];      // qkv hi (from gemm1)
__device__ __nv_bfloat16 g_qkvl[(size_t)BN * C3];      // qkv lo
__device__ __nv_bfloat16 g_xhi[(size_t)BN * CC];       // x split
__device__ __nv_bfloat16 g_xlo[(size_t)BN * CC];
__device__ __nv_bfloat16 g_chi[(size_t)BN * CC];       // ctx split (av output)
__device__ __nv_bfloat16 g_clo[(size_t)BN * CC];
__device__ __nv_bfloat16 g_wq_hi[(size_t)C3 * CC];     // Wqkv^T [2304][768]
__device__ __nv_bfloat16 g_wq_lo[(size_t)C3 * CC];
__device__ __nv_bfloat16 g_wp_hi[(size_t)CC * CC];     // Wproj^T [768][768]
__device__ __nv_bfloat16 g_wp_lo[(size_t)CC * CC];
__device__ __nv_bfloat16 g_ath[BHCNT * HD * HD];       // attn hi
__device__ __nv_bfloat16 g_atl[BHCNT * HD * HD];       // attn lo
__device__ float g_gram[BHCNT * HD * HD];
__device__ float g_qss[BHCNT * HD];
__device__ float g_kss[BHCNT * HD];

// ---------------------------------------------------------------------------
// Baseline-PTX helpers (sm_80+, no 'a'-gated features)
// ---------------------------------------------------------------------------
__device__ __forceinline__ uint32_t smem_u32(const void* p) {
    uint32_t a;
    asm("{ .reg .u64 t; cvta.to.shared.u64 t, %1; cvt.u32.u64 %0, t; }" : "=r"(a) : "l"(p));
    return a;
}
__device__ __forceinline__ void cp16(uint32_t saddr, const void* g) {
    asm volatile("cp.async.cg.shared.global [%0], [%1], 16;" :: "r"(saddr), "l"(g) : "memory");
}
__device__ __forceinline__ void cp_commit() {
    asm volatile("cp.async.commit_group;" ::: "memory");
}
__device__ __forceinline__ void cp_wait0() {
    asm volatile("cp.async.wait_group 0;" ::: "memory");
}
__device__ __forceinline__ void ldsm4(uint32_t& r0, uint32_t& r1, uint32_t& r2, uint32_t& r3,
                                      uint32_t addr) {
    asm volatile("ldmatrix.sync.aligned.m8n8.x4.shared.b16 {%0,%1,%2,%3}, [%4];"
                 : "=r"(r0), "=r"(r1), "=r"(r2), "=r"(r3) : "r"(addr));
}
__device__ __forceinline__ void ldsm4t(uint32_t& r0, uint32_t& r1, uint32_t& r2, uint32_t& r3,
                                       uint32_t addr) {
    asm volatile("ldmatrix.sync.aligned.m8n8.x4.trans.shared.b16 {%0,%1,%2,%3}, [%4];"
                 : "=r"(r0), "=r"(r1), "=r"(r2), "=r"(r3) : "r"(addr));
}
__device__ __forceinline__ void mma16816(float* d, const uint32_t* a, const uint32_t* b) {
    asm volatile(
        "mma.sync.aligned.m16n8k16.row.col.f32.bf16.bf16.f32 "
        "{%0,%1,%2,%3}, {%4,%5,%6,%7}, {%8,%9}, {%0,%1,%2,%3};"
        : "+f"(d[0]), "+f"(d[1]), "+f"(d[2]), "+f"(d[3])
        : "r"(a[0]), "r"(a[1]), "r"(a[2]), "r"(a[3]), "r"(b[0]), "r"(b[1]));
}
__device__ __forceinline__ uint32_t pk(__nv_bfloat16 a, __nv_bfloat16 b) {
    __nv_bfloat162 t = __halves2bfloat162(a, b);
    return *reinterpret_cast<uint32_t*>(&t);
}

// ---------------------------------------------------------------------------
// bf16 hi/lo split conversion for x (packed uint2 stores)
// ---------------------------------------------------------------------------
__global__ void conv_x_kernel(const float* __restrict__ x) {
    size_t i = (size_t)blockIdx.x * 256 + threadIdx.x;
    const size_t total = (size_t)BN * CC / 4;
    for (; i < total; i += (size_t)gridDim.x * 256) {
        float4 v = ((const float4*)x)[i];
        __nv_bfloat16 h0 = __float2bfloat16(v.x), h1 = __float2bfloat16(v.y);
        __nv_bfloat16 h2 = __float2bfloat16(v.z), h3 = __float2bfloat16(v.w);
        __nv_bfloat16 l0 = __float2bfloat16(v.x - __bfloat162float(h0));
        __nv_bfloat16 l1 = __float2bfloat16(v.y - __bfloat162float(h1));
        __nv_bfloat16 l2 = __float2bfloat16(v.z - __bfloat162float(h2));
        __nv_bfloat16 l3 = __float2bfloat16(v.w - __bfloat162float(h3));
        ((uint2*)g_xhi)[i] = make_uint2(pk(h0, h1), pk(h2, h3));
        ((uint2*)g_xlo)[i] = make_uint2(pk(l0, l1), pk(l2, l3));
    }
}

// ---------------------------------------------------------------------------
// Tiled transpose + hi/lo split: out[n][k] = W[k][n], W is [K][Nn].
// ---------------------------------------------------------------------------
__global__ __launch_bounds__(256) void transp_kernel(
    const float* __restrict__ W,
    __nv_bfloat16* __restrict__ Thi, __nv_bfloat16* __restrict__ Tlo,
    int K, int Nn)
{
    __shared__ float sm[32][33];
    const int n0 = blockIdx.x * 32, k0 = blockIdx.y * 32;
    const int c = threadIdx.x & 31, r = threadIdx.x >> 5;

#pragma unroll
    for (int rr = 0; rr < 4; rr++)
        sm[r + rr * 8][c] = W[(size_t)(k0 + r + rr * 8) * Nn + n0 + c];
    __syncthreads();

#pragma unroll
    for (int rr = 0; rr < 4; rr++) {
        const int n = n0 + r + rr * 8;
        const float v = sm[c][r + rr * 8];
        __nv_bfloat16 h = __float2bfloat16(v);
        Thi[(size_t)n * K + k0 + c] = h;
        Tlo[(size_t)n * K + k0 + c] = __float2bfloat16(v - __bfloat162float(h));
    }
}

// ---------------------------------------------------------------------------
// Zero reduction scratch (before gemm1: qss/kss; before gram_tc: gram)
// ---------------------------------------------------------------------------
__global__ void zero_kernel() {
    int i = blockIdx.x * 256 + threadIdx.x;
    if (i < BHCNT * HD * HD) g_gram[i] = 0.0f;
    if (i < BHCNT * HD) { g_qss[i] = 0.0f; g_kss[i] = 0.0f; }
}

// ---------------------------------------------------------------------------
// HMMA bf16-split GEMM, 3-stage cp.async pipeline (R13-proven mainloop).
// If Chi != null: write bf16 hi/lo output + fused q/k column sum-of-squares.
// Else: write fp32 C (+bias).
// ---------------------------------------------------------------------------
#define GEMM_SMEM_BYTES 98304
#define NCHUNK 36

__global__ __launch_bounds__(256) void gemm_mma(
    const __nv_bfloat16* __restrict__ Ahi, const __nv_bfloat16* __restrict__ Alo,
    const __nv_bfloat16* __restrict__ Bhi, const __nv_bfloat16* __restrict__ Blo,
    float* __restrict__ C, const float* __restrict__ bias, int ldc,
    __nv_bfloat16* __restrict__ Chi, __nv_bfloat16* __restrict__ Clo)
{
    extern __shared__ char smem[];
    const uint32_t sb = smem_u32(smem);
    const int t = threadIdx.x;
    const int lane = t & 31, wid = t >> 5;
    const int m0 = blockIdx.y * 128;
    const int n0 = blockIdx.x * 128;
    const int wm = (wid & 1) * 64;
    const int wn = (wid >> 1) * 32;

    int lso[4], lgo[4];
#pragma unroll
    for (int i = 0; i < 4; i++) {
        int idx = t + 256 * i, row = idx >> 3, seg = idx & 7;
        lso[i] = row * 128 + ((seg * 16) ^ ((row & 7) << 4));
        lgo[i] = row * CC + seg * 8;
    }

    const int q = lane >> 3, r = lane & 7;
    const uint32_t rx = (uint32_t)(r << 4);
    const int aro = r + (q & 1) * 8;
    const int akb = (q >> 1) * 16;
    const int bro = r + (q >> 1) * 8;
    const int bkb = (q & 1) * 16;
    uint32_t Ab0[4], Bb0[2];
#pragma unroll
    for (int mt = 0; mt < 4; mt++)
        Ab0[mt] = sb + (uint32_t)(wm + mt * 16 + aro) * 128u;
#pragma unroll
    for (int n2 = 0; n2 < 2; n2++)
        Bb0[n2] = sb + 16384u + (uint32_t)(wn + n2 * 16 + bro) * 128u;

    float acc[4][4][4];
#pragma unroll
    for (int mt = 0; mt < 4; mt++)
#pragma unroll
        for (int nt = 0; nt < 4; nt++)
#pragma unroll
            for (int i = 0; i < 4; i++) acc[mt][nt][i] = 0.0f;

#pragma unroll
    for (int i = 0; i < 4; i++) {
        cp16(sb + lso[i],          Ahi + (size_t)m0 * CC + lgo[i]);
        cp16(sb + 16384u + lso[i], Bhi + (size_t)n0 * CC + lgo[i]);
    }
    cp_commit();
#pragma unroll
    for (int i = 0; i < 4; i++) {
        cp16(sb + 32768u + lso[i],          Ahi + (size_t)m0 * CC + 64 + lgo[i]);
        cp16(sb + 32768u + 16384u + lso[i], Bhi + (size_t)n0 * CC + 64 + lgo[i]);
    }
    cp_commit();

    int s = 0;
    for (int c = 0; c < NCHUNK; c++) {
        if (c + 1 < NCHUNK) {
            asm volatile("cp.async.wait_group 1;" ::: "memory");
        } else {
            asm volatile("cp.async.wait_group 0;" ::: "memory");
        }
        __syncthreads();

        if (c + 2 < NCHUNK) {
            const int pn = c + 2;
            const int pass = pn / 12;
            const int k0 = (pn - pass * 12) * 64;
            const __nv_bfloat16* Ap = (pass == 2) ? Alo : Ahi;
            const __nv_bfloat16* Bp = (pass == 1) ? Blo : Bhi;
            const int s2 = (s + 2 >= 3) ? (s - 1) : (s + 2);
            const uint32_t st = sb + (uint32_t)s2 * 32768u;
#pragma unroll
            for (int i = 0; i < 4; i++) {
                cp16(st + lso[i],          Ap + (size_t)m0 * CC + k0 + lgo[i]);
                cp16(st + 16384u + lso[i], Bp + (size_t)n0 * CC + k0 + lgo[i]);
            }
            cp_commit();
        }

        const uint32_t so = (uint32_t)s * 32768u;
#pragma unroll
        for (int kk = 0; kk < 4; kk++) {
            const uint32_t ak = so + (((uint32_t)(kk * 32 + akb)) ^ rx);
            const uint32_t bk = so + (((uint32_t)(kk * 32 + bkb)) ^ rx);
            uint32_t a[4][4];
#pragma unroll
            for (int mt = 0; mt < 4; mt++)
                ldsm4(a[mt][0], a[mt][1], a[mt][2], a[mt][3], Ab0[mt] + ak);
            uint32_t bfr[4][2];
#pragma unroll
            for (int n2 = 0; n2 < 2; n2++) {
                uint32_t r0, r1, r2, r3;
                ldsm4(r0, r1, r2, r3, Bb0[n2] + bk);
                bfr[n2 * 2][0] = r0;     bfr[n2 * 2][1] = r1;
                bfr[n2 * 2 + 1][0] = r2; bfr[n2 * 2 + 1][1] = r3;
            }
#pragma unroll
            for (int nt = 0; nt < 4; nt++)
#pragma unroll
                for (int mt = 0; mt < 4; mt++)
                    mma16816(acc[mt][nt], a[mt], bfr[nt]);
        }

        s = (s == 2) ? 0 : (s + 1);
    }

    const int mrow = lane >> 2;
    const int ncol = (lane & 3) * 2;

    if (Chi != nullptr) {
        // bf16 hi/lo epilogue + fused q/k column sum-of-squares
        const int b = m0 >> 12;
#pragma unroll
        for (int nt = 0; nt < 4; nt++) {
            const int c0 = n0 + wn + nt * 8 + ncol;
            float s0 = 0.0f, s1 = 0.0f;
#pragma unroll
            for (int mt = 0; mt < 4; mt++) {
                const int m = m0 + wm + mt * 16 + mrow;
                const float v00 = acc[mt][nt][0], v01 = acc[mt][nt][1];
                const float v10 = acc[mt][nt][2], v11 = acc[mt][nt][3];
                __nv_bfloat16 h00 = __float2bfloat16(v00), h01 = __float2bfloat16(v01);
                __nv_bfloat16 h10 = __float2bfloat16(v10), h11 = __float2bfloat16(v11);
                *(uint32_t*)(Chi + (size_t)m * ldc + c0)       = pk(h00, h01);
                *(uint32_t*)(Chi + (size_t)(m + 8) * ldc + c0) = pk(h10, h11);
                *(uint32_t*)(Clo + (size_t)m * ldc + c0) =
                    pk(__float2bfloat16(v00 - __bfloat162float(h00)),
                       __float2bfloat16(v01 - __bfloat162float(h01)));
                *(uint32_t*)(Clo + (size_t)(m + 8) * ldc + c0) =
                    pk(__float2bfloat16(v10 - __bfloat162float(h10)),
                       __float2bfloat16(v11 - __bfloat162float(h11)));
                s0 += v00 * v00 + v10 * v10;
                s1 += v01 * v01 + v11 * v11;
            }
            if (c0 < 2 * CC) {   // q or k region (uniform per warp)
                s0 += __shfl_xor_sync(0xffffffff, s0, 4);
                s0 += __shfl_xor_sync(0xffffffff, s0, 8);
                s0 += __shfl_xor_sync(0xffffffff, s0, 16);
                s1 += __shfl_xor_sync(0xffffffff, s1, 4);
                s1 += __shfl_xor_sync(0xffffffff, s1, 8);
                s1 += __shfl_xor_sync(0xffffffff, s1, 16);
                if (lane < 4) {
                    const int cc0 = n0 + wn + nt * 8 + lane * 2;
                    float* dst = (cc0 < CC) ? g_qss : g_kss;
                    const int cr = (cc0 < CC) ? cc0 : cc0 - CC;
                    const int idx = (b * HH + cr / HD) * HD + (cr % HD);
                    atomicAdd(&dst[idx], s0);
                    atomicAdd(&dst[idx + 1], s1);
                }
            }
        }
    } else {
        // fp32 epilogue (+bias)
#pragma unroll
        for (int nt = 0; nt < 4; nt++) {
            const int col = n0 + wn + nt * 8 + ncol;
            float b0 = 0.0f, b1 = 0.0f;
            if (bias != nullptr) { b0 = bias[col]; b1 = bias[col + 1]; }
#pragma unroll
            for (int mt = 0; mt < 4; mt++) {
                const int m = m0 + wm + mt * 16 + mrow;
                float2 v0 = make_float2(acc[mt][nt][0] + b0, acc[mt][nt][1] + b1);
                float2 v1 = make_float2(acc[mt][nt][2] + b0, acc[mt][nt][3] + b1);
                *(float2*)(C + (size_t)m * ldc + col) = v0;
                *(float2*)(C + (size_t)(m + 8) * ldc + col) = v1;
            }
        }
    }
}

// ---------------------------------------------------------------------------
// gram_tc: per (b,h) G[d][e] += sum_n q[n,d]*k[n,e] via HMMA.
// Both operands loaded with ldmatrix.trans ([n][d] storage -> [d][n] frags).
// 3-term bf16 hi/lo. grid (64, 8 splits), block 128 (4 warps x 24 e-cols).
// ---------------------------------------------------------------------------
#define GP  104     // smem pitch, elements
#define GPB 208     // bytes
#define GRAM_SMEM 53248

__global__ __launch_bounds__(128) void gram_tc() {
    extern __shared__ char sm[];
    const uint32_t sb = smem_u32(sm);
    const uint32_t sqh = sb, sql = sb + 13312u, skh = sb + 26624u, skl = sb + 39936u;
    const int t = threadIdx.x, lane = t & 31, w = t >> 5;
    const int bh = blockIdx.x, b = bh >> 3, h = bh & 7;
    const int tok0 = blockIdx.y * 512;

    const __nv_bfloat16* qh = g_qkvh + ((size_t)b * NN + tok0) * C3 + h * HD;
    const __nv_bfloat16* ql = g_qkvl + ((size_t)b * NN + tok0) * C3 + h * HD;
    const __nv_bfloat16* kh = qh + CC;
    const __nv_bfloat16* kl = ql + CC;

    float acc[6][3][4];
#pragma unroll
    for (int mt = 0; mt < 6; mt++)
#pragma unroll
        for (int nt = 0; nt < 3; nt++)
#pragma unroll
            for (int i = 0; i < 4; i++) acc[mt][nt][i] = 0.0f;

    const int eb = w * 24;
    const int l8 = lane & 7, g4 = lane >> 3;
    // A trans lane addressing: rows nb+l8 (+8 for g2,g3), col +8 for g1,g3
    const int arow_off = l8 + ((g4 >> 1) & 1) * 8;
    const int acol_off = (g4 & 1) * 8;
    // B trans lane addressing: rows nb+l8 (+8 for g1,g3), col +8 for g2,g3
    const int brow_off = l8 + (g4 & 1) * 8;
    const int bcol_off = (g4 >> 1) * 8;

    for (int ch = 0; ch < 8; ch++) {
        const size_t g0 = (size_t)(ch * 64) * C3;
        for (int i = t; i < 3072; i += 128) {
            const int arr = i / 768, rem = i - arr * 768;
            const int rr = rem / 12, seg = rem - rr * 12;
            const __nv_bfloat16* src =
                (arr == 0) ? qh : (arr == 1) ? ql : (arr == 2) ? kh : kl;
            const uint32_t dst =
                ((arr == 0) ? sqh : (arr == 1) ? sql : (arr == 2) ? skh : skl);
            cp16(dst + rr * GPB + seg * 16, src + g0 + (size_t)rr * C3 + seg * 8);
        }
        cp_commit();
        cp_wait0();
        __syncthreads();

#pragma unroll
        for (int kk = 0; kk < 4; kk++) {
            const int nb = kk * 16;
            uint32_t ah[6][4], al[6][4];
#pragma unroll
            for (int mt = 0; mt < 6; mt++) {
                const uint32_t off = (uint32_t)(nb + arow_off) * GPB
                                   + (uint32_t)(mt * 16 + acol_off) * 2;
                ldsm4t(ah[mt][0], ah[mt][1], ah[mt][2], ah[mt][3], sqh + off);
                ldsm4t(al[mt][0], al[mt][1], al[mt][2], al[mt][3], sql + off);
            }
            uint32_t bh_[3][2], bl_[3][2];
            {
                uint32_t r0, r1, r2, r3;
                const uint32_t ro = (uint32_t)(nb + brow_off) * GPB;
                ldsm4t(r0, r1, r2, r3, skh + ro + (uint32_t)(eb + bcol_off) * 2);
                bh_[0][0] = r0; bh_[0][1] = r1; bh_[1][0] = r2; bh_[1][1] = r3;
                ldsm4t(r0, r1, r2, r3, skh + ro + (uint32_t)(eb + 16 + bcol_off) * 2);
                bh_[2][0] = r0; bh_[2][1] = r1;   // r2,r3 discarded (padding cols)
                ldsm4t(r0, r1, r2, r3, skl + ro + (uint32_t)(eb + bcol_off) * 2);
                bl_[0][0] = r0; bl_[0][1] = r1; bl_[1][0] = r2; bl_[1][1] = r3;
                ldsm4t(r0, r1, r2, r3, skl + ro + (uint32_t)(eb + 16 + bcol_off) * 2);
                bl_[2][0] = r0; bl_[2][1] = r1;
            }
#pragma unroll
            for (int nt = 0; nt < 3; nt++)
#pragma unroll
                for (int mt = 0; mt < 6; mt++) {
                    mma16816(acc[mt][nt], ah[mt], bh_[nt]);
                    mma16816(acc[mt][nt], ah[mt], bl_[nt]);
                    mma16816(acc[mt][nt], al[mt], bh_[nt]);
                }
        }
        __syncthreads();
    }

    float* G = g_gram + bh * HD * HD;
    const int r4 = lane >> 2, c2 = (lane & 3) * 2;
#pragma unroll
    for (int mt = 0; mt < 6; mt++)
#pragma unroll
        for (int nt = 0; nt < 3; nt++) {
            const int d = mt * 16 + r4, e = eb + nt * 8 + c2;
            atomicAdd(&G[d * HD + e],           acc[mt][nt][0]);
            atomicAdd(&G[d * HD + e + 1],       acc[mt][nt][1]);
            atomicAdd(&G[(d + 8) * HD + e],     acc[mt][nt][2]);
            atomicAdd(&G[(d + 8) * HD + e + 1], acc[mt][nt][3]);
        }
}

// ---------------------------------------------------------------------------
// Softmax with folded norms + temperature; emits attn as bf16 hi/lo.
// ---------------------------------------------------------------------------
__global__ void softmax_kernel(const float* __restrict__ temperature) {
    __shared__ float buf[96][97];
    __shared__ float invk[96];
    __shared__ float invq[96];
    const int bh = blockIdx.x;
    const int h  = bh & 7;
    const int t  = threadIdx.x;

    if (t < 96) {
        invq[t] = 1.0f / fmaxf(sqrtf(g_qss[bh * HD + t]), 1e-12f);
        invk[t] = 1.0f / fmaxf(sqrtf(g_kss[bh * HD + t]), 1e-12f);
    }
    __syncthreads();

    if (t < 96) {
        const float tmp = temperature[h];
        const float* Grow = g_gram + bh * HD * HD + t * HD;
        const float sd = tmp * invq[t];

        float m = -1e30f;
        for (int e = 0; e < 96; e++) {
            float v = Grow[e] * sd * invk[e];
            m = fmaxf(m, v);
        }
        float sum = 0.0f;
        for (int e = 0; e < 96; e++) {
            float v = expf(Grow[e] * sd * invk[e] - m);
            buf[t][e] = v;
            sum += v;
        }
        const float inv = 1.0f / sum;
        for (int e2 = 0; e2 < 48; e2++) {
            const float v0 = buf[t][e2 * 2] * inv;
            const float v1 = buf[t][e2 * 2 + 1] * inv;
            __nv_bfloat16 h0 = __float2bfloat16(v0), h1 = __float2bfloat16(v1);
            *(uint32_t*)(g_ath + bh * HD * HD + t * HD + e2 * 2) = pk(h0, h1);
            *(uint32_t*)(g_atl + bh * HD * HD + t * HD + e2 * 2) =
                pk(__float2bfloat16(v0 - __bfloat162float(h0)),
                   __float2bfloat16(v1 - __bfloat162float(h1)));
        }
    }
}

// ---------------------------------------------------------------------------
// av_tc: ctx[n][d] = sum_e V[n][e]*attn[d][e] via HMMA (row.col, no trans).
// 3-term bf16 hi/lo; writes ctx hi/lo for gemm2.
// grid (64, 32 token-chunks of 128), block 256 (8 warps x 16 tokens).
// ---------------------------------------------------------------------------
#define AV_SMEM 93184

__global__ __launch_bounds__(256) void av_tc() {
    extern __shared__ char sm[];
    const uint32_t sb = smem_u32(sm);
    const uint32_t sath = sb, satl = sb + 19968u, svh = sb + 39936u, svl = sb + 66560u;
    const int t = threadIdx.x, lane = t & 31, w = t >> 5;
    const int bh = blockIdx.x, b = bh >> 3, h = bh & 7;
    const int tok0 = blockIdx.y * 128;

    const __nv_bfloat16* vh = g_qkvh + ((size_t)b * NN + tok0) * C3 + 2 * CC + h * HD;
    const __nv_bfloat16* vl = g_qkvl + ((size_t)b * NN + tok0) * C3 + 2 * CC + h * HD;

    // attn: 96 rows x 12 seg x 2 arrays
    for (int i = t; i < 2304; i += 256) {
        const int arr = i / 1152, rem = i - arr * 1152;
        const int rr = rem / 12, seg = rem - rr * 12;
        const __nv_bfloat16* src = (arr ? g_atl : g_ath) + bh * HD * HD + rr * HD + seg * 8;
        cp16((arr ? satl : sath) + rr * GPB + seg * 16, src);
    }
    // V: 128 rows x 12 seg x 2 arrays
    for (int i = t; i < 3072; i += 256) {
        const int arr = i / 1536, rem = i - arr * 1536;
        const int rr = rem / 12, seg = rem - rr * 12;
        const __nv_bfloat16* src = (arr ? vl : vh) + (size_t)rr * C3 + seg * 8;
        cp16((arr ? svl : svh) + rr * GPB + seg * 16, src);
    }
    cp_commit();
    cp_wait0();
    __syncthreads();

    float acc[12][4];
#pragma unroll
    for (int nt = 0; nt < 12; nt++)
#pragma unroll
        for (int i = 0; i < 4; i++) acc[nt][i] = 0.0f;

    const int l8 = lane & 7, g4 = lane >> 3;
    const int var = w * 16 + l8 + (g4 & 1) * 8;   // A: rows, +8 for g1,g3
    const int vac = (g4 >> 1) * 8;                // A: col half for g2,g3
    const int bro = l8 + (g4 >> 1) * 8;           // B: rows, +8 for g2,g3
    const int bco = (g4 & 1) * 8;                 // B: col half for g1,g3

#pragma unroll
    for (int kk = 0; kk < 6; kk++) {
        const int e = kk * 16;
        uint32_t a_h[4], a_l[4];
        const uint32_t aoff = (uint32_t)var * GPB + (uint32_t)(e + vac) * 2;
        ldsm4(a_h[0], a_h[1], a_h[2], a_h[3], svh + aoff);
        ldsm4(a_l[0], a_l[1], a_l[2], a_l[3], svl + aoff);
#pragma unroll
        for (int g = 0; g < 6; g++) {
            const uint32_t boff = (uint32_t)(g * 16 + bro) * GPB + (uint32_t)(e + bco) * 2;
            uint32_t r0, r1, r2, r3;
            ldsm4(r0, r1, r2, r3, sath + boff);
            uint32_t bh0[2] = {r0, r1}, bh1[2] = {r2, r3};
            ldsm4(r0, r1, r2, r3, satl + boff);
            uint32_t bl0[2] = {r0, r1}, bl1[2] = {r2, r3};
            mma16816(acc[2 * g],     a_h, bh0);
            mma16816(acc[2 * g + 1], a_h, bh1);
            mma16816(acc[2 * g],     a_h, bl0);
            mma16816(acc[2 * g + 1], a_h, bl1);
            mma16816(acc[2 * g],     a_l, bh0);
            mma16816(acc[2 * g + 1], a_l, bh1);
        }
    }

    // epilogue: bf16 hi/lo packed stores into [B,N,C] ctx
    const int n = tok0 + w * 16 + (lane >> 2);
    const size_t base = ((size_t)b * NN + n) * CC + h * HD;
#pragma unroll
    for (int nt = 0; nt < 12; nt++) {
        const int d = nt * 8 + (lane & 3) * 2;
        const float v00 = acc[nt][0], v01 = acc[nt][1];
        const float v10 = acc[nt][2], v11 = acc[nt][3];
        __nv_bfloat16 h00 = __float2bfloat16(v00), h01 = __float2bfloat16(v01);
        __nv_bfloat16 h10 = __float2bfloat16(v10), h11 = __float2bfloat16(v11);
        *(uint32_t*)(g_chi + base + d)          = pk(h00, h01);
        *(uint32_t*)(g_chi + base + 8 * CC + d) = pk(h10, h11);
        *(uint32_t*)(g_clo + base + d) =
            pk(__float2bfloat16(v00 - __bfloat162float(h00)),
               __float2bfloat16(v01 - __bfloat162float(h01)));
        *(uint32_t*)(g_clo + base + 8 * CC + d) =
            pk(__float2bfloat16(v10 - __bfloat162float(h10)),
               __float2bfloat16(v11 - __bfloat162float(h11)));
    }
}

// ---------------------------------------------------------------------------
extern "C" void kernel_launch(void* const* d_in, const int* in_sizes, int n_in,
                              void* d_out, int out_size)
{
    const float* x     = (const float*)d_in[0];
    const float* Wqkv  = (const float*)d_in[1];
    const float* temp  = (const float*)d_in[2];
    const float* Wproj = (const float*)d_in[3];
    const float* bproj = (const float*)d_in[4];
    float* out = (float*)d_out;

    cudaFuncSetAttribute(gemm_mma, cudaFuncAttributeMaxDynamicSharedMemorySize,
                         GEMM_SMEM_BYTES);
    cudaFuncSetAttribute(gram_tc, cudaFuncAttributeMaxDynamicSharedMemorySize,
                         GRAM_SMEM);
    cudaFuncSetAttribute(av_tc, cudaFuncAttributeMaxDynamicSharedMemorySize,
                         AV_SMEM);

    __nv_bfloat16 *xhi, *xlo, *chi, *clo, *wqh, *wql, *wph, *wpl, *qvh, *qvl;
    cudaGetSymbolAddress((void**)&xhi, g_xhi);
    cudaGetSymbolAddress((void**)&xlo, g_xlo);
    cudaGetSymbolAddress((void**)&chi, g_chi);
    cudaGetSymbolAddress((void**)&clo, g_clo);
    cudaGetSymbolAddress((void**)&wqh, g_wq_hi);
    cudaGetSymbolAddress((void**)&wql, g_wq_lo);
    cudaGetSymbolAddress((void**)&wph, g_wp_hi);
    cudaGetSymbolAddress((void**)&wpl, g_wp_lo);
    cudaGetSymbolAddress((void**)&qvh, g_qkvh);
    cudaGetSymbolAddress((void**)&qvl, g_qkvl);

    // 1) split conversions + zero of atomic targets
    conv_x_kernel<<<1184, 256>>>(x);
    transp_kernel<<<dim3(C3 / 32, CC / 32), 256>>>(Wqkv, wqh, wql, CC, C3);
    transp_kernel<<<dim3(CC / 32, CC / 32), 256>>>(Wproj, wph, wpl, CC, CC);
    zero_kernel<<<(BHCNT * HD * HD + 255) / 256, 256>>>();

    // 2) qkv = x @ Wqkv -> bf16 hi/lo + fused q/k norms
    gemm_mma<<<dim3(C3 / 128, BN / 128), 256, GEMM_SMEM_BYTES>>>(
        xhi, xlo, wqh, wql, nullptr, nullptr, C3, qvh, qvl);

    // 3) attention middle, all-HMMA
    gram_tc<<<dim3(BHCNT, 8), 128, GRAM_SMEM>>>();
    softmax_kernel<<<BHCNT, 128>>>(temp);
    av_tc<<<dim3(BHCNT, 32), 256, AV_SMEM>>>();

    // 4) out = ctx @ Wproj + bias (fp32 epilogue)
    gemm_mma<<<dim3(CC / 128, BN / 128), 256, GEMM_SMEM_BYTES>>>(
        chi, clo, wph, wpl, out, bproj, CC, nullptr, nullptr);
}